// round 2
// baseline (speedup 1.0000x reference)
#include <cuda_runtime.h>

#define NN 50000
#define EE 800000
#define DD 64
#define HH 2
#define HC 128

// ---------------- scratch (device globals; no allocation allowed) ----------
__device__ float    g_x_src[(size_t)NN * HC];   // 25.6 MB
__device__ float    g_a_src[NN * HH];
__device__ float    g_a_dst[NN * HH];
__device__ unsigned g_umax [NN * HH];           // monotone-mapped float max
__device__ float    g_s    [NN * HH];
__device__ float    g_alpha[(size_t)EE * HH];   // alpha, then ex (in place)
__device__ float    g_agg  [(size_t)NN * HC];   // 25.6 MB
__device__ float    g_t1   [(size_t)NN * 64];   // dense stage 1 out
__device__ float    g_t2   [(size_t)NN * 64];   // dense stage 2 out
__device__ float    g_vedge[HH * DD];           // W_edge @ att_edge[h]
__device__ float    g_udst [HH * DD];           // W_lin  @ att_dst[h]

// order-preserving float<->uint mapping for atomic max
__device__ __forceinline__ unsigned fmap(float f) {
    unsigned u = __float_as_uint(f);
    return (f >= 0.f) ? (u | 0x80000000u) : ~u;
}
__device__ __forceinline__ float finv(unsigned u) {
    return (u & 0x80000000u) ? __uint_as_float(u & 0x7FFFFFFFu)
                             : __uint_as_float(~u);
}

// ---------------- kernels --------------------------------------------------

__global__ void k_zero() {
    int i = blockIdx.x * blockDim.x + threadIdx.x;
    int stride = gridDim.x * blockDim.x;
    for (int j = i; j < NN * HH; j += stride) { g_umax[j] = 0u; g_s[j] = 0.f; }
    for (int j = i; j < NN * HC; j += stride) { g_agg[j] = 0.f; }
}

// fold attention vectors through the weight matrices (tiny)
__global__ void k_vec(const float* __restrict__ Wlin, const float* __restrict__ attd,
                      const float* __restrict__ Wedge, const float* __restrict__ atte) {
    int t = threadIdx.x;
    if (t < 128) {
        int h = t >> 6, d = t & 63;
        float acc = 0.f;
        #pragma unroll 8
        for (int c = 0; c < 64; c++) acc += Wlin[d * 128 + h * 64 + c] * attd[h * 64 + c];
        g_udst[h * 64 + d] = acc;
    } else {
        int idx = t - 128;
        int h = idx >> 6, d = idx & 63;
        float acc = 0.f;
        #pragma unroll 8
        for (int c = 0; c < 64; c++) acc += Wedge[d * 128 + h * 64 + c] * atte[h * 64 + c];
        g_vedge[h * 64 + d] = acc;
    }
}

// per node: x_src = right @ W_lin ; a_src = x_src . att_src ; a_dst = left . u_dst
__global__ void k_node(const float* __restrict__ rf, const float* __restrict__ lf,
                       const float* __restrict__ Wlin, const float* __restrict__ atts) {
    __shared__ float Ws[8192];
    __shared__ float attS[128];
    __shared__ float row[64], lrow[64];
    __shared__ float part[128], pd0[64], pd1[64];
    int t = threadIdx.x;
    for (int i = t; i < 8192; i += 128) Ws[i] = Wlin[i];
    attS[t] = atts[t];
    for (int n = blockIdx.x; n < NN; n += gridDim.x) {
        __syncthreads();
        if (t < 64) { row[t] = rf[n * 64 + t]; lrow[t] = lf[n * 64 + t]; }
        __syncthreads();
        float acc = 0.f;
        #pragma unroll 16
        for (int kk = 0; kk < 64; kk++) acc += row[kk] * Ws[kk * 128 + t];
        g_x_src[(size_t)n * 128 + t] = acc;
        part[t] = acc * attS[t];
        if (t < 64) { pd0[t] = lrow[t] * g_udst[t]; pd1[t] = lrow[t] * g_udst[64 + t]; }
        __syncthreads();
        if (t == 0)       { float s = 0; for (int kk = 0;  kk < 64;  kk++) s += part[kk]; g_a_src[n * 2 + 0] = s; }
        else if (t == 32) { float s = 0; for (int kk = 64; kk < 128; kk++) s += part[kk]; g_a_src[n * 2 + 1] = s; }
        else if (t == 64) { float s = 0; for (int kk = 0;  kk < 64;  kk++) s += pd0[kk];  g_a_dst[n * 2 + 0] = s; }
        else if (t == 96) { float s = 0; for (int kk = 0;  kk < 64;  kk++) s += pd1[kk];  g_a_dst[n * 2 + 1] = s; }
    }
}

// per edge (warp): alpha = a_src[src] + a_dst[dst] + ef.v_edge ; leaky ; seg-max
__global__ void k_edge_alpha(const float* __restrict__ ef, const int* __restrict__ ei) {
    int wid  = (blockIdx.x * blockDim.x + threadIdx.x) >> 5;
    int lane = threadIdx.x & 31;
    if (wid >= EE) return;
    const float2* e2 = (const float2*)(ef + (size_t)wid * 64);
    float2 v = e2[lane];
    float p0 = v.x * g_vedge[2 * lane]      + v.y * g_vedge[2 * lane + 1];
    float p1 = v.x * g_vedge[64 + 2 * lane] + v.y * g_vedge[64 + 2 * lane + 1];
    #pragma unroll
    for (int o = 16; o > 0; o >>= 1) {
        p0 += __shfl_down_sync(0xffffffffu, p0, o);
        p1 += __shfl_down_sync(0xffffffffu, p1, o);
    }
    if (lane == 0) {
        int src = ei[wid], dst = ei[EE + wid];
        float a0 = g_a_src[src * 2 + 0] + g_a_dst[dst * 2 + 0] + p0;
        float a1 = g_a_src[src * 2 + 1] + g_a_dst[dst * 2 + 1] + p1;
        a0 = a0 > 0.f ? a0 : 0.2f * a0;
        a1 = a1 > 0.f ? a1 : 0.2f * a1;
        g_alpha[(size_t)wid * 2 + 0] = a0;
        g_alpha[(size_t)wid * 2 + 1] = a1;
        atomicMax(&g_umax[dst * 2 + 0], fmap(a0));
        atomicMax(&g_umax[dst * 2 + 1], fmap(a1));
    }
}

// per (edge, head): ex = exp(alpha - m[dst]); seg-sum; store ex in place
__global__ void k_exp(const int* __restrict__ ei) {
    int idx = blockIdx.x * blockDim.x + threadIdx.x;
    if (idx >= EE * HH) return;
    int e = idx >> 1, h = idx & 1;
    int dst = ei[EE + e];
    float m  = finv(g_umax[dst * 2 + h]);
    float ex = expf(g_alpha[idx] - m);
    g_alpha[idx] = ex;
    atomicAdd(&g_s[dst * 2 + h], ex);
}

// edge_index -> output (value cast to float)
__global__ void k_eout(const int* __restrict__ ei, float* __restrict__ out) {
    int i = blockIdx.x * blockDim.x + threadIdx.x;
    if (i < 2 * EE) out[NN * 64 + i] = (float)ei[i];
}

// per edge (warp): att = ex/(s+eps); write att; agg[dst] += att * x_src[src]
__global__ void k_msg(const int* __restrict__ ei, float* __restrict__ out, int hasAtt) {
    int wid  = (blockIdx.x * blockDim.x + threadIdx.x) >> 5;
    int lane = threadIdx.x & 31;
    if (wid >= EE) return;
    int src = ei[wid], dst = ei[EE + wid];
    int h = lane >> 4;
    float ex = g_alpha[(size_t)wid * 2 + h];
    float sv = g_s[dst * 2 + h];
    float att = ex / (sv + 1e-16f);
    if (hasAtt && ((lane & 15) == 0))
        out[(size_t)NN * 64 + 2 * EE + (size_t)wid * 2 + h] = att;
    float4 xs = *(const float4*)(g_x_src + (size_t)src * 128 + lane * 4);
    xs.x *= att; xs.y *= att; xs.z *= att; xs.w *= att;
    float* dp = g_agg + (size_t)dst * 128 + lane * 4;
    asm volatile("red.global.add.v4.f32 [%0], {%1,%2,%3,%4};"
                 :: "l"(dp), "f"(xs.x), "f"(xs.y), "f"(xs.z), "f"(xs.w) : "memory");
}

// dense stage 1: t1 = relu( relu(agg + bconv) @ W_lt + b_lt )   [N,128]->[N,64]
__global__ void k_dense1(const float* __restrict__ Wlt, const float* __restrict__ blt,
                         const float* __restrict__ bconv) {
    __shared__ float sW[8192];     // 32 KB
    __shared__ float sb[64];
    __shared__ float sbc[128];
    __shared__ float sr[4 * 128];
    int t = threadIdx.x;
    for (int i = t; i < 8192; i += 256) sW[i] = Wlt[i];
    if (t < 64)  sb[t] = blt[t];
    if (t < 128) sbc[t] = bconv[t];
    int g = t >> 6, j = t & 63;
    for (int n0 = blockIdx.x * 4; n0 < NN; n0 += gridDim.x * 4) {
        int node = n0 + g;
        __syncthreads();
        if (node < NN) {
            float v0 = g_agg[(size_t)node * 128 + j]      + sbc[j];
            float v1 = g_agg[(size_t)node * 128 + 64 + j] + sbc[64 + j];
            sr[g * 128 + j]      = v0 > 0.f ? v0 : 0.f;
            sr[g * 128 + 64 + j] = v1 > 0.f ? v1 : 0.f;
        }
        __syncthreads();
        float acc = sb[j];
        #pragma unroll 8
        for (int kk = 0; kk < 128; kk++) acc += sr[g * 128 + kk] * sW[kk * 64 + j];
        if (node < NN) g_t1[(size_t)node * 64 + j] = acc > 0.f ? acc : 0.f;
    }
}

// dense stage 2: t2 = t1 @ W_fm + b_fm     [N,64]->[N,64]   (t1 already relu'd)
__global__ void k_dense2(const float* __restrict__ Wfm, const float* __restrict__ bfm) {
    __shared__ float sW[4096];     // 16 KB
    __shared__ float sb[64];
    __shared__ float sr[4 * 64];
    int t = threadIdx.x;
    for (int i = t; i < 4096; i += 256) sW[i] = Wfm[i];
    if (t < 64) sb[t] = bfm[t];
    int g = t >> 6, j = t & 63;
    for (int n0 = blockIdx.x * 4; n0 < NN; n0 += gridDim.x * 4) {
        int node = n0 + g;
        __syncthreads();
        if (node < NN) sr[g * 64 + j] = g_t1[(size_t)node * 64 + j];
        __syncthreads();
        float acc = sb[j];
        #pragma unroll 8
        for (int kk = 0; kk < 64; kk++) acc += sr[g * 64 + kk] * sW[kk * 64 + j];
        if (node < NN) g_t2[(size_t)node * 64 + j] = acc;
    }
}

// dense stage 3: out = concat(lf, t2) @ W_pc + b_pc    [N,128]->[N,64]
__global__ void k_dense3(const float* __restrict__ lf,
                         const float* __restrict__ Wpc, const float* __restrict__ bpc,
                         float* __restrict__ out) {
    __shared__ float sW[8192];     // 32 KB
    __shared__ float sb[64];
    __shared__ float sr[4 * 128];
    int t = threadIdx.x;
    for (int i = t; i < 8192; i += 256) sW[i] = Wpc[i];
    if (t < 64) sb[t] = bpc[t];
    int g = t >> 6, j = t & 63;
    for (int n0 = blockIdx.x * 4; n0 < NN; n0 += gridDim.x * 4) {
        int node = n0 + g;
        __syncthreads();
        if (node < NN) {
            sr[g * 128 + j]      = lf[(size_t)node * 64 + j];
            sr[g * 128 + 64 + j] = g_t2[(size_t)node * 64 + j];
        }
        __syncthreads();
        float acc = sb[j];
        #pragma unroll 8
        for (int kk = 0; kk < 128; kk++) acc += sr[g * 128 + kk] * sW[kk * 64 + j];
        if (node < NN) out[(size_t)node * 64 + j] = acc;
    }
}

// ---------------- launch ---------------------------------------------------
extern "C" void kernel_launch(void* const* d_in, const int* in_sizes, int n_in,
                              void* d_out, int out_size) {
    // inputs in dict order; scalar scatter_out_size may or may not be present
    int k = (n_in >= 17) ? 5 : 4;
    const float* lf    = (const float*)d_in[0];
    const int*   ei    = (const int*)  d_in[1];
    const float* ef    = (const float*)d_in[2];
    const float* rf    = (const float*)d_in[3];
    const float* Wlin  = (const float*)d_in[k + 0];
    const float* atts  = (const float*)d_in[k + 1];
    const float* attd  = (const float*)d_in[k + 2];
    const float* Wedge = (const float*)d_in[k + 3];
    const float* atte  = (const float*)d_in[k + 4];
    const float* bconv = (const float*)d_in[k + 5];
    const float* Wlt   = (const float*)d_in[k + 6];
    const float* blt   = (const float*)d_in[k + 7];
    const float* Wfm   = (const float*)d_in[k + 8];
    const float* bfm   = (const float*)d_in[k + 9];
    const float* Wpc   = (const float*)d_in[k + 10];
    const float* bpc   = (const float*)d_in[k + 11];
    float* out = (float*)d_out;

    int hasEi  = out_size >= NN * 64 + 2 * EE;
    int hasAtt = out_size >= NN * 64 + 2 * EE + 2 * EE;

    k_zero<<<2048, 256>>>();
    k_vec<<<1, 256>>>(Wlin, attd, Wedge, atte);
    k_node<<<592, 128>>>(rf, lf, Wlin, atts);
    k_edge_alpha<<<(EE + 7) / 8, 256>>>(ef, ei);
    k_exp<<<(EE * 2 + 255) / 256, 256>>>(ei);
    if (hasEi) k_eout<<<(2 * EE + 255) / 256, 256>>>(ei, out);
    k_msg<<<(EE + 7) / 8, 256>>>(ei, out, hasAtt);
    k_dense1<<<296, 256>>>(Wlt, blt, bconv);
    k_dense2<<<296, 256>>>(Wfm, bfm);
    k_dense3<<<296, 256>>>(lf, Wpc, bpc, out);
}

// round 3
// speedup vs baseline: 1.5384x; 1.5384x over previous
#include <cuda_runtime.h>

#define NN 50000
#define EE 800000
#define DD 64
#define HH 2
#define HC 128

// ---------------- scratch (device globals; no allocation allowed) ----------
__device__ float g_x_src[(size_t)NN * HC];   // 25.6 MB  projected src features
__device__ float g_a_src[NN * HH];
__device__ float g_a_dst[NN * HH];
__device__ float g_alpha[(size_t)EE * HH];   // alpha -> unnormalized exp (in place)
__device__ float g_agg  [(size_t)NN * HC];   // 25.6 MB  aggregated messages
__device__ float g_t1   [(size_t)NN * 64];
__device__ float g_t2   [(size_t)NN * 64];
__device__ float g_vedge[HH * DD];           // W_edge @ att_edge[h]
__device__ float g_udst [HH * DD];           // W_lin  @ att_dst[h]
__device__ int   g_deg  [NN];                // per-dst degree
__device__ int   g_rs   [NN + 1];            // CSR row starts
__device__ int   g_cur  [NN];                // fill cursors
__device__ int   g_csr  [EE];                // edge ids grouped by dst

// ---------------- kernels --------------------------------------------------

__global__ void k_zero() {
    int i = blockIdx.x * blockDim.x + threadIdx.x;
    if (i < NN) g_deg[i] = 0;
}

// fold attention vectors through the weight matrices (tiny)
__global__ void k_vec(const float* __restrict__ Wlin, const float* __restrict__ attd,
                      const float* __restrict__ Wedge, const float* __restrict__ atte) {
    int t = threadIdx.x;
    if (t < 128) {
        int h = t >> 6, d = t & 63;
        float acc = 0.f;
        #pragma unroll 8
        for (int c = 0; c < 64; c++) acc += Wlin[d * 128 + h * 64 + c] * attd[h * 64 + c];
        g_udst[h * 64 + d] = acc;
    } else {
        int idx = t - 128;
        int h = idx >> 6, d = idx & 63;
        float acc = 0.f;
        #pragma unroll 8
        for (int c = 0; c < 64; c++) acc += Wedge[d * 128 + h * 64 + c] * atte[h * 64 + c];
        g_vedge[h * 64 + d] = acc;
    }
}

// per node: x_src = right @ W_lin ; a_src = x_src . att_src ; a_dst = left . u_dst
__global__ void k_node(const float* __restrict__ rf, const float* __restrict__ lf,
                       const float* __restrict__ Wlin, const float* __restrict__ atts) {
    __shared__ float Ws[8192];
    __shared__ float attS[128];
    __shared__ float row[64], lrow[64];
    __shared__ float part[128], pd0[64], pd1[64];
    int t = threadIdx.x;
    int w = t >> 5, lane = t & 31;
    for (int i = t; i < 8192; i += 128) Ws[i] = Wlin[i];
    attS[t] = atts[t];
    for (int n = blockIdx.x; n < NN; n += gridDim.x) {
        __syncthreads();
        if (t < 64) { row[t] = rf[n * 64 + t]; lrow[t] = lf[n * 64 + t]; }
        __syncthreads();
        float acc = 0.f;
        #pragma unroll 16
        for (int kk = 0; kk < 64; kk++) acc += row[kk] * Ws[kk * 128 + t];
        g_x_src[(size_t)n * 128 + t] = acc;
        part[t] = acc * attS[t];
        if (t < 64) { pd0[t] = lrow[t] * g_udst[t]; pd1[t] = lrow[t] * g_udst[64 + t]; }
        __syncthreads();
        float v;
        if      (w == 0) v = part[lane] + part[lane + 32];
        else if (w == 1) v = part[64 + lane] + part[96 + lane];
        else if (w == 2) v = pd0[lane] + pd0[lane + 32];
        else             v = pd1[lane] + pd1[lane + 32];
        #pragma unroll
        for (int o = 16; o > 0; o >>= 1) v += __shfl_xor_sync(0xffffffffu, v, o);
        if (lane == 0) {
            if      (w == 0) g_a_src[n * 2 + 0] = v;
            else if (w == 1) g_a_src[n * 2 + 1] = v;
            else if (w == 2) g_a_dst[n * 2 + 0] = v;
            else             g_a_dst[n * 2 + 1] = v;
        }
    }
}

// 16 lanes per edge: alpha = a_src[src]+a_dst[dst]+ef.v_edge ; leaky ; deg histogram
__global__ void k_edge_alpha(const float* __restrict__ ef, const int* __restrict__ ei) {
    __shared__ float sv[128];
    int t = threadIdx.x;
    if (t < 128) sv[t] = g_vedge[t];
    __syncthreads();
    int e = blockIdx.x * 16 + (t >> 4);
    int g = t & 15;
    if (e >= EE) return;
    float4 v = ((const float4*)ef)[(size_t)e * 16 + g];
    float p0 = v.x * sv[4 * g] + v.y * sv[4 * g + 1] + v.z * sv[4 * g + 2] + v.w * sv[4 * g + 3];
    float p1 = v.x * sv[64 + 4 * g] + v.y * sv[64 + 4 * g + 1] + v.z * sv[64 + 4 * g + 2] + v.w * sv[64 + 4 * g + 3];
    #pragma unroll
    for (int o = 8; o > 0; o >>= 1) {
        p0 += __shfl_xor_sync(0xffffffffu, p0, o);
        p1 += __shfl_xor_sync(0xffffffffu, p1, o);
    }
    if (g == 0) {
        int src = ei[e], dst = ei[EE + e];
        float a0 = g_a_src[src * 2 + 0] + g_a_dst[dst * 2 + 0] + p0;
        float a1 = g_a_src[src * 2 + 1] + g_a_dst[dst * 2 + 1] + p1;
        a0 = a0 > 0.f ? a0 : 0.2f * a0;
        a1 = a1 > 0.f ? a1 : 0.2f * a1;
        ((float2*)g_alpha)[e] = make_float2(a0, a1);
        atomicAdd(&g_deg[dst], 1);
    }
}

// single-block exclusive scan of g_deg -> g_rs, g_cur
__global__ void k_scan() {
    __shared__ int spart[1024];
    const int CH = (NN + 1023) / 1024;  // 49
    int t = threadIdx.x;
    int base = t * CH;
    int s = 0;
    for (int i = 0; i < CH; i++) {
        int idx = base + i;
        if (idx < NN) s += g_deg[idx];
    }
    spart[t] = s;
    __syncthreads();
    for (int off = 1; off < 1024; off <<= 1) {
        int v = (t >= off) ? spart[t - off] : 0;
        __syncthreads();
        spart[t] += v;
        __syncthreads();
    }
    int run = (t > 0) ? spart[t - 1] : 0;
    for (int i = 0; i < CH; i++) {
        int idx = base + i;
        if (idx < NN) {
            g_rs[idx] = run;
            g_cur[idx] = run;
            run += g_deg[idx];
        }
    }
    if (t == 1023) g_rs[NN] = run;
}

// scatter edge ids into CSR; also emit edge_index (float) into output
__global__ void k_fill(const int* __restrict__ ei, float* __restrict__ out, int hasEi) {
    int e = blockIdx.x * blockDim.x + threadIdx.x;
    if (e >= EE) return;
    int src = ei[e], dst = ei[EE + e];
    int pos = atomicAdd(&g_cur[dst], 1);
    g_csr[pos] = e;
    if (hasEi) {
        out[NN * 64 + e]      = (float)src;
        out[NN * 64 + EE + e] = (float)dst;
    }
}

// warp per dst: softmax over its edges + gather-aggregate messages
__global__ void k_gat(const int* __restrict__ ei, float* __restrict__ out, int hasAtt) {
    int warp = (blockIdx.x * blockDim.x + threadIdx.x) >> 5;
    int lane = threadIdx.x & 31;
    if (warp >= NN) return;
    int dst = warp;
    int beg = g_rs[dst], end = g_rs[dst + 1];
    const float2* alpha2 = (const float2*)g_alpha;
    // pass 1: max per head
    float m0 = -1e30f, m1 = -1e30f;
    for (int i = beg + lane; i < end; i += 32) {
        float2 a = alpha2[g_csr[i]];
        m0 = fmaxf(m0, a.x);
        m1 = fmaxf(m1, a.y);
    }
    #pragma unroll
    for (int o = 16; o > 0; o >>= 1) {
        m0 = fmaxf(m0, __shfl_xor_sync(0xffffffffu, m0, o));
        m1 = fmaxf(m1, __shfl_xor_sync(0xffffffffu, m1, o));
    }
    // pass 2: exp + sum; store unnormalized exp back into g_alpha
    float s0 = 0.f, s1 = 0.f;
    for (int i = beg + lane; i < end; i += 32) {
        int eid = g_csr[i];
        float2 a = alpha2[eid];
        float e0 = __expf(a.x - m0), e1 = __expf(a.y - m1);
        s0 += e0; s1 += e1;
        ((float2*)g_alpha)[eid] = make_float2(e0, e1);
    }
    #pragma unroll
    for (int o = 16; o > 0; o >>= 1) {
        s0 += __shfl_xor_sync(0xffffffffu, s0, o);
        s1 += __shfl_xor_sync(0xffffffffu, s1, o);
    }
    float r0 = 1.f / (s0 + 1e-16f), r1 = 1.f / (s1 + 1e-16f);
    __syncwarp();
    // pass 3: messages; lane owns columns lane*4 .. lane*4+3 (head = lane>>4)
    int h = lane >> 4;
    float rh = h ? r1 : r0;
    float4 acc = make_float4(0.f, 0.f, 0.f, 0.f);
    for (int i = beg; i < end; i++) {
        int eid = g_csr[i];                    // broadcast
        int src = ei[eid];                     // broadcast
        float2 eab = alpha2[eid];              // broadcast (e0, e1)
        if (hasAtt && lane == 0) {
            ((float2*)(out + (size_t)NN * 64 + 2 * EE))[eid] =
                make_float2(eab.x * r0, eab.y * r1);
        }
        float att = (h ? eab.y : eab.x) * rh;
        float4 x = ((const float4*)g_x_src)[(size_t)src * 32 + lane];
        acc.x += att * x.x; acc.y += att * x.y;
        acc.z += att * x.z; acc.w += att * x.w;
    }
    ((float4*)g_agg)[(size_t)dst * 32 + lane] = acc;
}

// dense stage 1: t1 = relu( relu(agg + bconv) @ W_lt + b_lt )   [N,128]->[N,64]
__global__ void k_dense1(const float* __restrict__ Wlt, const float* __restrict__ blt,
                         const float* __restrict__ bconv) {
    __shared__ float sW[8192];
    __shared__ float sb[64];
    __shared__ float sbc[128];
    __shared__ float sr[4 * 128];
    int t = threadIdx.x;
    for (int i = t; i < 8192; i += 256) sW[i] = Wlt[i];
    if (t < 64)  sb[t] = blt[t];
    if (t < 128) sbc[t] = bconv[t];
    int g = t >> 6, j = t & 63;
    for (int n0 = blockIdx.x * 4; n0 < NN; n0 += gridDim.x * 4) {
        int node = n0 + g;
        __syncthreads();
        if (node < NN) {
            float v0 = g_agg[(size_t)node * 128 + j]      + sbc[j];
            float v1 = g_agg[(size_t)node * 128 + 64 + j] + sbc[64 + j];
            sr[g * 128 + j]      = v0 > 0.f ? v0 : 0.f;
            sr[g * 128 + 64 + j] = v1 > 0.f ? v1 : 0.f;
        }
        __syncthreads();
        float acc = sb[j];
        #pragma unroll 8
        for (int kk = 0; kk < 128; kk++) acc += sr[g * 128 + kk] * sW[kk * 64 + j];
        if (node < NN) g_t1[(size_t)node * 64 + j] = acc > 0.f ? acc : 0.f;
    }
}

// dense stage 2: t2 = t1 @ W_fm + b_fm     [N,64]->[N,64]
__global__ void k_dense2(const float* __restrict__ Wfm, const float* __restrict__ bfm) {
    __shared__ float sW[4096];
    __shared__ float sb[64];
    __shared__ float sr[4 * 64];
    int t = threadIdx.x;
    for (int i = t; i < 4096; i += 256) sW[i] = Wfm[i];
    if (t < 64) sb[t] = bfm[t];
    int g = t >> 6, j = t & 63;
    for (int n0 = blockIdx.x * 4; n0 < NN; n0 += gridDim.x * 4) {
        int node = n0 + g;
        __syncthreads();
        if (node < NN) sr[g * 64 + j] = g_t1[(size_t)node * 64 + j];
        __syncthreads();
        float acc = sb[j];
        #pragma unroll 8
        for (int kk = 0; kk < 64; kk++) acc += sr[g * 64 + kk] * sW[kk * 64 + j];
        if (node < NN) g_t2[(size_t)node * 64 + j] = acc;
    }
}

// dense stage 3: out = concat(lf, t2) @ W_pc + b_pc    [N,128]->[N,64]
__global__ void k_dense3(const float* __restrict__ lf,
                         const float* __restrict__ Wpc, const float* __restrict__ bpc,
                         float* __restrict__ out) {
    __shared__ float sW[8192];
    __shared__ float sb[64];
    __shared__ float sr[4 * 128];
    int t = threadIdx.x;
    for (int i = t; i < 8192; i += 256) sW[i] = Wpc[i];
    if (t < 64) sb[t] = bpc[t];
    int g = t >> 6, j = t & 63;
    for (int n0 = blockIdx.x * 4; n0 < NN; n0 += gridDim.x * 4) {
        int node = n0 + g;
        __syncthreads();
        if (node < NN) {
            sr[g * 128 + j]      = lf[(size_t)node * 64 + j];
            sr[g * 128 + 64 + j] = g_t2[(size_t)node * 64 + j];
        }
        __syncthreads();
        float acc = sb[j];
        #pragma unroll 8
        for (int kk = 0; kk < 128; kk++) acc += sr[g * 128 + kk] * sW[kk * 64 + j];
        if (node < NN) out[(size_t)node * 64 + j] = acc;
    }
}

// ---------------- launch ---------------------------------------------------
extern "C" void kernel_launch(void* const* d_in, const int* in_sizes, int n_in,
                              void* d_out, int out_size) {
    int k = (n_in >= 17) ? 5 : 4;
    const float* lf    = (const float*)d_in[0];
    const int*   ei    = (const int*)  d_in[1];
    const float* ef    = (const float*)d_in[2];
    const float* rf    = (const float*)d_in[3];
    const float* Wlin  = (const float*)d_in[k + 0];
    const float* atts  = (const float*)d_in[k + 1];
    const float* attd  = (const float*)d_in[k + 2];
    const float* Wedge = (const float*)d_in[k + 3];
    const float* atte  = (const float*)d_in[k + 4];
    const float* bconv = (const float*)d_in[k + 5];
    const float* Wlt   = (const float*)d_in[k + 6];
    const float* blt   = (const float*)d_in[k + 7];
    const float* Wfm   = (const float*)d_in[k + 8];
    const float* bfm   = (const float*)d_in[k + 9];
    const float* Wpc   = (const float*)d_in[k + 10];
    const float* bpc   = (const float*)d_in[k + 11];
    float* out = (float*)d_out;

    int hasEi  = out_size >= NN * 64 + 2 * EE;
    int hasAtt = out_size >= NN * 64 + 2 * EE + 2 * EE;

    k_zero<<<(NN + 255) / 256, 256>>>();
    k_vec<<<1, 256>>>(Wlin, attd, Wedge, atte);
    k_node<<<592, 128>>>(rf, lf, Wlin, atts);
    k_edge_alpha<<<(EE + 15) / 16, 256>>>(ef, ei);
    k_scan<<<1, 1024>>>();
    k_fill<<<(EE + 255) / 256, 256>>>(ei, out, hasEi);
    k_gat<<<(NN + 7) / 8, 256>>>(ei, out, hasAtt);
    k_dense1<<<296, 256>>>(Wlt, blt, bconv);
    k_dense2<<<296, 256>>>(Wfm, bfm);
    k_dense3<<<296, 256>>>(lf, Wpc, bpc, out);
}

// round 4
// speedup vs baseline: 1.5740x; 1.0231x over previous
#include <cuda_runtime.h>

#define NN 50000
#define EE 800000
#define DD 64
#define HH 2
#define HC 128

// ---------------- scratch (device globals; no allocation allowed) ----------
__device__ float  g_x_src[(size_t)NN * HC];   // 25.6 MB  projected src features
__device__ float  g_a_src[NN * HH];
__device__ float  g_a_dst[NN * HH];
__device__ float2 g_ex2 [EE];                 // exp(leaky(alpha)) by edge id
__device__ float2 g_exs [EE];                 // same, CSR (dst-grouped) order
__device__ int    g_srcs[EE];                 // src node ids, CSR order
__device__ float2 g_r   [NN];                 // per-dst 1/(sum+eps) per head
__device__ float  g_agg [(size_t)NN * HC];    // 25.6 MB aggregated messages
__device__ float  g_t1  [(size_t)NN * 64];
__device__ float  g_t2  [(size_t)NN * 64];
__device__ float  g_vedge[HH * DD];           // W_edge @ att_edge[h]
__device__ float  g_udst [HH * DD];           // W_lin  @ att_dst[h]
__device__ int    g_deg [NN];
__device__ int    g_rs  [NN + 1];
__device__ int    g_cur [NN];

// ---------------- kernels --------------------------------------------------

__global__ void k_zero() {
    int i = blockIdx.x * blockDim.x + threadIdx.x;
    if (i < NN) g_deg[i] = 0;
}

// fold attention vectors through the weight matrices (tiny)
__global__ void k_vec(const float* __restrict__ Wlin, const float* __restrict__ attd,
                      const float* __restrict__ Wedge, const float* __restrict__ atte) {
    int t = threadIdx.x;
    if (t < 128) {
        int h = t >> 6, d = t & 63;
        float acc = 0.f;
        #pragma unroll 8
        for (int c = 0; c < 64; c++) acc += Wlin[d * 128 + h * 64 + c] * attd[h * 64 + c];
        g_udst[h * 64 + d] = acc;
    } else {
        int idx = t - 128;
        int h = idx >> 6, d = idx & 63;
        float acc = 0.f;
        #pragma unroll 8
        for (int c = 0; c < 64; c++) acc += Wedge[d * 128 + h * 64 + c] * atte[h * 64 + c];
        g_vedge[h * 64 + d] = acc;
    }
}

// per node: x_src = right @ W_lin ; a_src = x_src . att_src ; a_dst = left . u_dst
__global__ void k_node(const float* __restrict__ rf, const float* __restrict__ lf,
                       const float* __restrict__ Wlin, const float* __restrict__ atts) {
    __shared__ float Ws[8192];
    __shared__ float attS[128];
    __shared__ float row[64], lrow[64];
    __shared__ float part[128], pd0[64], pd1[64];
    int t = threadIdx.x;
    int w = t >> 5, lane = t & 31;
    for (int i = t; i < 8192; i += 128) Ws[i] = Wlin[i];
    attS[t] = atts[t];
    for (int n = blockIdx.x; n < NN; n += gridDim.x) {
        __syncthreads();
        if (t < 64) { row[t] = rf[n * 64 + t]; lrow[t] = lf[n * 64 + t]; }
        __syncthreads();
        float acc = 0.f;
        #pragma unroll 16
        for (int kk = 0; kk < 64; kk++) acc += row[kk] * Ws[kk * 128 + t];
        g_x_src[(size_t)n * 128 + t] = acc;
        part[t] = acc * attS[t];
        if (t < 64) { pd0[t] = lrow[t] * g_udst[t]; pd1[t] = lrow[t] * g_udst[64 + t]; }
        __syncthreads();
        float v;
        if      (w == 0) v = part[lane] + part[lane + 32];
        else if (w == 1) v = part[64 + lane] + part[96 + lane];
        else if (w == 2) v = pd0[lane] + pd0[lane + 32];
        else             v = pd1[lane] + pd1[lane + 32];
        #pragma unroll
        for (int o = 16; o > 0; o >>= 1) v += __shfl_xor_sync(0xffffffffu, v, o);
        if (lane == 0) {
            if      (w == 0) g_a_src[n * 2 + 0] = v;
            else if (w == 1) g_a_src[n * 2 + 1] = v;
            else if (w == 2) g_a_dst[n * 2 + 0] = v;
            else             g_a_dst[n * 2 + 1] = v;
        }
    }
}

// 16 lanes per edge: alpha = a_src+a_dst+ef.vedge ; leaky ; exp ; deg histogram
__global__ void k_edge_alpha(const float* __restrict__ ef, const int* __restrict__ ei) {
    __shared__ float sv[128];
    int t = threadIdx.x;
    if (t < 128) sv[t] = g_vedge[t];
    __syncthreads();
    int e = blockIdx.x * 16 + (t >> 4);
    int g = t & 15;
    if (e >= EE) return;
    float4 v = ((const float4*)ef)[(size_t)e * 16 + g];
    float p0 = v.x * sv[4 * g] + v.y * sv[4 * g + 1] + v.z * sv[4 * g + 2] + v.w * sv[4 * g + 3];
    float p1 = v.x * sv[64 + 4 * g] + v.y * sv[64 + 4 * g + 1] + v.z * sv[64 + 4 * g + 2] + v.w * sv[64 + 4 * g + 3];
    // combined two-head reduction over 16 lanes:
    // after step: lanes g<8 carry p0 partials, lanes g>=8 carry p1 partials
    float a = __shfl_xor_sync(0xffffffffu, p0, 8);
    float b = __shfl_xor_sync(0xffffffffu, p1, 8);
    float r = (g & 8) ? (p1 + b) : (p0 + a);
    r += __shfl_xor_sync(0xffffffffu, r, 4);
    r += __shfl_xor_sync(0xffffffffu, r, 2);
    r += __shfl_xor_sync(0xffffffffu, r, 1);
    float other = __shfl_xor_sync(0xffffffffu, r, 8);   // lane g==0 gets p1 sum
    if (g == 0) {
        int src = ei[e], dst = ei[EE + e];
        float2 as = ((const float2*)g_a_src)[src];
        float2 ad = ((const float2*)g_a_dst)[dst];
        float a0 = as.x + ad.x + r;
        float a1 = as.y + ad.y + other;
        a0 = a0 > 0.f ? a0 : 0.2f * a0;
        a1 = a1 > 0.f ? a1 : 0.2f * a1;
        g_ex2[e] = make_float2(__expf(a0), __expf(a1));
        atomicAdd(&g_deg[dst], 1);
    }
}

// single-block exclusive scan of g_deg -> g_rs, g_cur
__global__ void k_scan() {
    __shared__ int spart[1024];
    const int CH = (NN + 1023) / 1024;  // 49
    int t = threadIdx.x;
    int base = t * CH;
    int s = 0;
    for (int i = 0; i < CH; i++) {
        int idx = base + i;
        if (idx < NN) s += g_deg[idx];
    }
    spart[t] = s;
    __syncthreads();
    for (int off = 1; off < 1024; off <<= 1) {
        int v = (t >= off) ? spart[t - off] : 0;
        __syncthreads();
        spart[t] += v;
        __syncthreads();
    }
    int run = (t > 0) ? spart[t - 1] : 0;
    for (int i = 0; i < CH; i++) {
        int idx = base + i;
        if (idx < NN) {
            g_rs[idx] = run;
            g_cur[idx] = run;
            run += g_deg[idx];
        }
    }
    if (t == 1023) g_rs[NN] = run;
}

// scatter (src, exp pair) into CSR order; also emit edge_index (float) output
__global__ void k_fill(const int* __restrict__ ei, float* __restrict__ out, int hasEi) {
    int e = blockIdx.x * blockDim.x + threadIdx.x;
    if (e >= EE) return;
    int src = ei[e], dst = ei[EE + e];
    int pos = atomicAdd(&g_cur[dst], 1);
    g_srcs[pos] = src;
    g_exs[pos]  = g_ex2[e];
    if (hasEi) {
        out[NN * 64 + e]      = (float)src;
        out[NN * 64 + EE + e] = (float)dst;
    }
}

// warp per dst: sum exp per head, then gather-aggregate messages (unroll 4)
__global__ void k_gat() {
    int dst  = (blockIdx.x * blockDim.x + threadIdx.x) >> 5;
    int lane = threadIdx.x & 31;
    if (dst >= NN) return;
    int beg = g_rs[dst], end = g_rs[dst + 1];
    // pass A: sums
    float s0 = 0.f, s1 = 0.f;
    for (int i = beg + lane; i < end; i += 32) {
        float2 ev = g_exs[i];
        s0 += ev.x; s1 += ev.y;
    }
    float a = __shfl_xor_sync(0xffffffffu, s0, 16);
    float b = __shfl_xor_sync(0xffffffffu, s1, 16);
    float v = (lane & 16) ? (s1 + b) : (s0 + a);
    v += __shfl_xor_sync(0xffffffffu, v, 8);
    v += __shfl_xor_sync(0xffffffffu, v, 4);
    v += __shfl_xor_sync(0xffffffffu, v, 2);
    v += __shfl_xor_sync(0xffffffffu, v, 1);
    float S0 = __shfl_sync(0xffffffffu, v, 0);
    float S1 = __shfl_sync(0xffffffffu, v, 16);
    float r0 = 1.f / (S0 + 1e-16f), r1 = 1.f / (S1 + 1e-16f);
    if (lane == 0) g_r[dst] = make_float2(r0, r1);
    // pass B: lane owns 4 columns (head = lane>>4)
    int h = lane >> 4;
    float rh = h ? r1 : r0;
    float4 acc = make_float4(0.f, 0.f, 0.f, 0.f);
    const float4* X = (const float4*)g_x_src;
    int i = beg;
    for (; i + 4 <= end; i += 4) {
        int sA = g_srcs[i], sB = g_srcs[i + 1], sC = g_srcs[i + 2], sD = g_srcs[i + 3];
        float2 eA = g_exs[i], eB = g_exs[i + 1], eC = g_exs[i + 2], eD = g_exs[i + 3];
        float4 xA = X[(size_t)sA * 32 + lane];
        float4 xB = X[(size_t)sB * 32 + lane];
        float4 xC = X[(size_t)sC * 32 + lane];
        float4 xD = X[(size_t)sD * 32 + lane];
        float aA = (h ? eA.y : eA.x) * rh;
        float aB = (h ? eB.y : eB.x) * rh;
        float aC = (h ? eC.y : eC.x) * rh;
        float aD = (h ? eD.y : eD.x) * rh;
        acc.x += aA * xA.x + aB * xB.x + aC * xC.x + aD * xD.x;
        acc.y += aA * xA.y + aB * xB.y + aC * xC.y + aD * xD.y;
        acc.z += aA * xA.z + aB * xB.z + aC * xC.z + aD * xD.z;
        acc.w += aA * xA.w + aB * xB.w + aC * xC.w + aD * xD.w;
    }
    for (; i < end; i++) {
        int sA = g_srcs[i];
        float2 eA = g_exs[i];
        float aA = (h ? eA.y : eA.x) * rh;
        float4 xA = X[(size_t)sA * 32 + lane];
        acc.x += aA * xA.x; acc.y += aA * xA.y;
        acc.z += aA * xA.z; acc.w += aA * xA.w;
    }
    ((float4*)g_agg)[(size_t)dst * 32 + lane] = acc;
}

// edge-parallel, coalesced: att output
__global__ void k_att(const int* __restrict__ ei, float* __restrict__ out) {
    int e = blockIdx.x * blockDim.x + threadIdx.x;
    if (e >= EE) return;
    int dst = ei[EE + e];
    float2 rv = g_r[dst];
    float2 ev = g_ex2[e];
    ((float2*)(out + (size_t)NN * 64 + 2 * EE))[e] = make_float2(ev.x * rv.x, ev.y * rv.y);
}

// dense stage 1: t1 = relu( relu(agg + bconv) @ W_lt + b_lt )   [N,128]->[N,64]
__global__ void k_dense1(const float* __restrict__ Wlt, const float* __restrict__ blt,
                         const float* __restrict__ bconv) {
    __shared__ float sW[8192];
    __shared__ float sb[64];
    __shared__ float sbc[128];
    __shared__ float sr[4 * 128];
    int t = threadIdx.x;
    for (int i = t; i < 8192; i += 256) sW[i] = Wlt[i];
    if (t < 64)  sb[t] = blt[t];
    if (t < 128) sbc[t] = bconv[t];
    int g = t >> 6, j = t & 63;
    for (int n0 = blockIdx.x * 4; n0 < NN; n0 += gridDim.x * 4) {
        int node = n0 + g;
        __syncthreads();
        if (node < NN) {
            float v0 = g_agg[(size_t)node * 128 + j]      + sbc[j];
            float v1 = g_agg[(size_t)node * 128 + 64 + j] + sbc[64 + j];
            sr[g * 128 + j]      = v0 > 0.f ? v0 : 0.f;
            sr[g * 128 + 64 + j] = v1 > 0.f ? v1 : 0.f;
        }
        __syncthreads();
        float acc = sb[j];
        #pragma unroll 8
        for (int kk = 0; kk < 128; kk++) acc += sr[g * 128 + kk] * sW[kk * 64 + j];
        if (node < NN) g_t1[(size_t)node * 64 + j] = acc > 0.f ? acc : 0.f;
    }
}

// dense stage 2: t2 = t1 @ W_fm + b_fm     [N,64]->[N,64]
__global__ void k_dense2(const float* __restrict__ Wfm, const float* __restrict__ bfm) {
    __shared__ float sW[4096];
    __shared__ float sb[64];
    __shared__ float sr[4 * 64];
    int t = threadIdx.x;
    for (int i = t; i < 4096; i += 256) sW[i] = Wfm[i];
    if (t < 64) sb[t] = bfm[t];
    int g = t >> 6, j = t & 63;
    for (int n0 = blockIdx.x * 4; n0 < NN; n0 += gridDim.x * 4) {
        int node = n0 + g;
        __syncthreads();
        if (node < NN) sr[g * 64 + j] = g_t1[(size_t)node * 64 + j];
        __syncthreads();
        float acc = sb[j];
        #pragma unroll 8
        for (int kk = 0; kk < 64; kk++) acc += sr[g * 64 + kk] * sW[kk * 64 + j];
        if (node < NN) g_t2[(size_t)node * 64 + j] = acc;
    }
}

// dense stage 3: out = concat(lf, t2) @ W_pc + b_pc    [N,128]->[N,64]
__global__ void k_dense3(const float* __restrict__ lf,
                         const float* __restrict__ Wpc, const float* __restrict__ bpc,
                         float* __restrict__ out) {
    __shared__ float sW[8192];
    __shared__ float sb[64];
    __shared__ float sr[4 * 128];
    int t = threadIdx.x;
    for (int i = t; i < 8192; i += 256) sW[i] = Wpc[i];
    if (t < 64) sb[t] = bpc[t];
    int g = t >> 6, j = t & 63;
    for (int n0 = blockIdx.x * 4; n0 < NN; n0 += gridDim.x * 4) {
        int node = n0 + g;
        __syncthreads();
        if (node < NN) {
            sr[g * 128 + j]      = lf[(size_t)node * 64 + j];
            sr[g * 128 + 64 + j] = g_t2[(size_t)node * 64 + j];
        }
        __syncthreads();
        float acc = sb[j];
        #pragma unroll 8
        for (int kk = 0; kk < 128; kk++) acc += sr[g * 128 + kk] * sW[kk * 64 + j];
        if (node < NN) out[(size_t)node * 64 + j] = acc;
    }
}

// ---------------- launch ---------------------------------------------------
extern "C" void kernel_launch(void* const* d_in, const int* in_sizes, int n_in,
                              void* d_out, int out_size) {
    int k = (n_in >= 17) ? 5 : 4;
    const float* lf    = (const float*)d_in[0];
    const int*   ei    = (const int*)  d_in[1];
    const float* ef    = (const float*)d_in[2];
    const float* rf    = (const float*)d_in[3];
    const float* Wlin  = (const float*)d_in[k + 0];
    const float* atts  = (const float*)d_in[k + 1];
    const float* attd  = (const float*)d_in[k + 2];
    const float* Wedge = (const float*)d_in[k + 3];
    const float* atte  = (const float*)d_in[k + 4];
    const float* bconv = (const float*)d_in[k + 5];
    const float* Wlt   = (const float*)d_in[k + 6];
    const float* blt   = (const float*)d_in[k + 7];
    const float* Wfm   = (const float*)d_in[k + 8];
    const float* bfm   = (const float*)d_in[k + 9];
    const float* Wpc   = (const float*)d_in[k + 10];
    const float* bpc   = (const float*)d_in[k + 11];
    float* out = (float*)d_out;

    int hasEi  = out_size >= NN * 64 + 2 * EE;
    int hasAtt = out_size >= NN * 64 + 2 * EE + 2 * EE;

    k_zero<<<(NN + 255) / 256, 256>>>();
    k_vec<<<1, 256>>>(Wlin, attd, Wedge, atte);
    k_node<<<592, 128>>>(rf, lf, Wlin, atts);
    k_edge_alpha<<<(EE + 15) / 16, 256>>>(ef, ei);
    k_scan<<<1, 1024>>>();
    k_fill<<<(EE + 255) / 256, 256>>>(ei, out, hasEi);
    k_gat<<<(NN + 7) / 8, 256>>>();
    if (hasAtt) k_att<<<(EE + 255) / 256, 256>>>(ei, out);
    k_dense1<<<296, 256>>>(Wlt, blt, bconv);
    k_dense2<<<296, 256>>>(Wfm, bfm);
    k_dense3<<<296, 256>>>(lf, Wpc, bpc, out);
}

// round 5
// speedup vs baseline: 2.0294x; 1.2894x over previous
#include <cuda_runtime.h>

#define NN 50000
#define EE 800000
#define DD 64
#define HH 2
#define HC 128

// ---------------- scratch ----------------
__device__ float  g_x_src[(size_t)NN * HC];   // projected src features
__device__ float  g_a_src[NN * HH];
__device__ float  g_a_dst[NN * HH];
__device__ float2 g_ex2 [EE];                 // exp(leaky(alpha)) by edge id
__device__ float2 g_exs [EE];                 // normalized att, CSR order
__device__ int    g_srcs[EE];                 // src ids, CSR order
__device__ float2 g_sum2[NN];                 // per-dst sum of exp
__device__ float  g_agg [(size_t)NN * HC];
__device__ float  g_t1  [(size_t)NN * 64];
__device__ float  g_t2  [(size_t)NN * 64];
__device__ float  g_vedge[HH * DD];
__device__ float  g_udst [HH * DD];
__device__ int    g_deg [NN];
__device__ int    g_rs  [NN + 1];
__device__ int    g_cur [NN];

// ---------------- kernels ----------------

__global__ void k_zero() {
    int i = blockIdx.x * blockDim.x + threadIdx.x;
    if (i < NN) { g_deg[i] = 0; g_sum2[i] = make_float2(0.f, 0.f); }
}

__global__ void k_vec(const float* __restrict__ Wlin, const float* __restrict__ attd,
                      const float* __restrict__ Wedge, const float* __restrict__ atte) {
    int t = threadIdx.x;
    if (t < 128) {
        int h = t >> 6, d = t & 63;
        float acc = 0.f;
        #pragma unroll 8
        for (int c = 0; c < 64; c++) acc += Wlin[d * 128 + h * 64 + c] * attd[h * 64 + c];
        g_udst[h * 64 + d] = acc;
    } else {
        int idx = t - 128;
        int h = idx >> 6, d = idx & 63;
        float acc = 0.f;
        #pragma unroll 8
        for (int c = 0; c < 64; c++) acc += Wedge[d * 128 + h * 64 + c] * atte[h * 64 + c];
        g_vedge[h * 64 + d] = acc;
    }
}

// register-tiled: x_src = rf @ Wlin (50000x64x128) + a_src reduction
// 256 thr = 8 nodes (1 warp each) x 32 colgroups (4 cols)
__global__ void k_node(const float* __restrict__ rf, const float* __restrict__ Wlin,
                       const float* __restrict__ atts) {
    __shared__ float sW[64 * 128];
    __shared__ float sF[8 * 68];
    __shared__ float sA[128];
    int t = threadIdx.x;
    for (int i = t; i < 8192; i += 256) sW[i] = Wlin[i];
    if (t < 128) sA[t] = atts[t];
    int cg = t & 31, nl = t >> 5;
    for (int base = blockIdx.x * 8; base < NN; base += gridDim.x * 8) {
        __syncthreads();
        for (int i = t; i < 512; i += 256) {
            int n = i >> 6, k = i & 63, nd = base + n;
            sF[n * 68 + k] = (nd < NN) ? rf[(size_t)nd * 64 + k] : 0.f;
        }
        __syncthreads();
        float4 acc = make_float4(0.f, 0.f, 0.f, 0.f);
        #pragma unroll 4
        for (int k = 0; k < 64; k += 4) {
            float4 f4 = *(const float4*)&sF[nl * 68 + k];
            float4 w0 = ((const float4*)sW)[(k    ) * 32 + cg];
            float4 w1 = ((const float4*)sW)[(k + 1) * 32 + cg];
            float4 w2 = ((const float4*)sW)[(k + 2) * 32 + cg];
            float4 w3 = ((const float4*)sW)[(k + 3) * 32 + cg];
            acc.x += f4.x * w0.x + f4.y * w1.x + f4.z * w2.x + f4.w * w3.x;
            acc.y += f4.x * w0.y + f4.y * w1.y + f4.z * w2.y + f4.w * w3.y;
            acc.z += f4.x * w0.z + f4.y * w1.z + f4.z * w2.z + f4.w * w3.z;
            acc.w += f4.x * w0.w + f4.y * w1.w + f4.z * w2.w + f4.w * w3.w;
        }
        int node = base + nl;
        if (node < NN) {           // warp-uniform
            ((float4*)g_x_src)[(size_t)node * 32 + cg] = acc;
            float4 a4 = ((const float4*)sA)[cg];
            float part = acc.x * a4.x + acc.y * a4.y + acc.z * a4.z + acc.w * a4.w;
            part += __shfl_xor_sync(0xffffffffu, part, 8);
            part += __shfl_xor_sync(0xffffffffu, part, 4);
            part += __shfl_xor_sync(0xffffffffu, part, 2);
            part += __shfl_xor_sync(0xffffffffu, part, 1);
            if (cg == 0)  g_a_src[node * 2 + 0] = part;
            if (cg == 16) g_a_src[node * 2 + 1] = part;
        }
    }
}

// a_dst = lf . udst per head; warp per node (16 active lanes, float4)
__global__ void k_adst(const float* __restrict__ lf) {
    __shared__ float su[128];
    int t = threadIdx.x;
    if (t < 128) su[t] = g_udst[t];
    __syncthreads();
    int lane = t & 31;
    for (int n = blockIdx.x * 8 + (t >> 5); n < NN; n += gridDim.x * 8) {
        float d0 = 0.f, d1 = 0.f;
        if (lane < 16) {
            float4 v  = ((const float4*)lf)[(size_t)n * 16 + lane];
            float4 u0 = ((const float4*)su)[lane];
            float4 u1 = ((const float4*)su)[16 + lane];
            d0 = v.x * u0.x + v.y * u0.y + v.z * u0.z + v.w * u0.w;
            d1 = v.x * u1.x + v.y * u1.y + v.z * u1.z + v.w * u1.w;
        }
        d0 += __shfl_xor_sync(0xffffffffu, d0, 8);
        d0 += __shfl_xor_sync(0xffffffffu, d0, 4);
        d0 += __shfl_xor_sync(0xffffffffu, d0, 2);
        d0 += __shfl_xor_sync(0xffffffffu, d0, 1);
        d1 += __shfl_xor_sync(0xffffffffu, d1, 8);
        d1 += __shfl_xor_sync(0xffffffffu, d1, 4);
        d1 += __shfl_xor_sync(0xffffffffu, d1, 2);
        d1 += __shfl_xor_sync(0xffffffffu, d1, 1);
        if (lane == 0) ((float2*)g_a_dst)[n] = make_float2(d0, d1);
    }
}

// 4 lanes per edge (MLP=4): alpha -> leaky -> exp ; accumulate deg + sums
__global__ void k_edge_alpha(const float* __restrict__ ef, const int* __restrict__ ei) {
    __shared__ float sv[128];
    int t = threadIdx.x;
    if (t < 128) sv[t] = g_vedge[t];
    __syncthreads();
    int e = blockIdx.x * 64 + (t >> 2);
    int g = t & 3;
    const float4* E4 = (const float4*)ef;
    float4 v0 = E4[(size_t)e * 16 + g];
    float4 v1 = E4[(size_t)e * 16 + g + 4];
    float4 v2 = E4[(size_t)e * 16 + g + 8];
    float4 v3 = E4[(size_t)e * 16 + g + 12];
    const float4* S4 = (const float4*)sv;
    float4 s0, s1;
    float p0 = 0.f, p1 = 0.f;
    s0 = S4[g];      s1 = S4[16 + g];
    p0 += v0.x*s0.x + v0.y*s0.y + v0.z*s0.z + v0.w*s0.w;
    p1 += v0.x*s1.x + v0.y*s1.y + v0.z*s1.z + v0.w*s1.w;
    s0 = S4[g + 4];  s1 = S4[20 + g];
    p0 += v1.x*s0.x + v1.y*s0.y + v1.z*s0.z + v1.w*s0.w;
    p1 += v1.x*s1.x + v1.y*s1.y + v1.z*s1.z + v1.w*s1.w;
    s0 = S4[g + 8];  s1 = S4[24 + g];
    p0 += v2.x*s0.x + v2.y*s0.y + v2.z*s0.z + v2.w*s0.w;
    p1 += v2.x*s1.x + v2.y*s1.y + v2.z*s1.z + v2.w*s1.w;
    s0 = S4[g + 12]; s1 = S4[28 + g];
    p0 += v3.x*s0.x + v3.y*s0.y + v3.z*s0.z + v3.w*s0.w;
    p1 += v3.x*s1.x + v3.y*s1.y + v3.z*s1.z + v3.w*s1.w;
    // combined two-head reduction over 4 lanes
    float a = __shfl_xor_sync(0xffffffffu, p0, 2);
    float b = __shfl_xor_sync(0xffffffffu, p1, 2);
    float r = (g & 2) ? (p1 + b) : (p0 + a);
    r += __shfl_xor_sync(0xffffffffu, r, 1);
    float other = __shfl_xor_sync(0xffffffffu, r, 2);
    if (g == 0) {
        int src = ei[e], dst = ei[EE + e];
        float2 as = ((const float2*)g_a_src)[src];
        float2 ad = ((const float2*)g_a_dst)[dst];
        float a0 = as.x + ad.x + r;
        float a1 = as.y + ad.y + other;
        a0 = a0 > 0.f ? a0 : 0.2f * a0;
        a1 = a1 > 0.f ? a1 : 0.2f * a1;
        float e0 = __expf(a0), e1 = __expf(a1);
        g_ex2[e] = make_float2(e0, e1);
        atomicAdd(&g_deg[dst], 1);
        atomicAdd(&g_sum2[dst].x, e0);
        atomicAdd(&g_sum2[dst].y, e1);
    }
}

// single-block exclusive scan of g_deg -> g_rs, g_cur
__global__ void k_scan() {
    __shared__ int spart[1024];
    const int CH = (NN + 1023) / 1024;  // 49
    int t = threadIdx.x;
    int base = t * CH;
    int s = 0;
    #pragma unroll 7
    for (int i = 0; i < CH; i++) {
        int idx = base + i;
        if (idx < NN) s += g_deg[idx];
    }
    spart[t] = s;
    __syncthreads();
    for (int off = 1; off < 1024; off <<= 1) {
        int v = (t >= off) ? spart[t - off] : 0;
        __syncthreads();
        spart[t] += v;
        __syncthreads();
    }
    int run = (t > 0) ? spart[t - 1] : 0;
    for (int i = 0; i < CH; i++) {
        int idx = base + i;
        if (idx < NN) {
            g_rs[idx] = run;
            g_cur[idx] = run;
            run += g_deg[idx];
        }
    }
    if (t == 1023) g_rs[NN] = run;
}

// CSR fill with normalized attention; emit edge_index + att outputs coalesced
__global__ void k_fill(const int* __restrict__ ei, float* __restrict__ out,
                       int hasEi, int hasAtt) {
    int e = blockIdx.x * blockDim.x + threadIdx.x;
    if (e >= EE) return;
    int src = ei[e], dst = ei[EE + e];
    float2 ex = g_ex2[e];
    float2 sm = g_sum2[dst];
    float2 att = make_float2(ex.x / (sm.x + 1e-16f), ex.y / (sm.y + 1e-16f));
    int pos = atomicAdd(&g_cur[dst], 1);
    g_srcs[pos] = src;
    g_exs[pos]  = att;
    if (hasAtt)
        ((float2*)(out + (size_t)NN * 64 + 2 * EE))[e] = att;
    if (hasEi) {
        out[NN * 64 + e]      = (float)src;
        out[NN * 64 + EE + e] = (float)dst;
    }
}

// warp per dst: single gather-accumulate pass (att pre-normalized)
__global__ void k_gat() {
    int dst  = (blockIdx.x * blockDim.x + threadIdx.x) >> 5;
    int lane = threadIdx.x & 31;
    if (dst >= NN) return;
    int beg = g_rs[dst], end = g_rs[dst + 1];
    int h = lane >> 4;
    float4 acc = make_float4(0.f, 0.f, 0.f, 0.f);
    const float4* X = (const float4*)g_x_src;
    int i = beg;
    for (; i + 4 <= end; i += 4) {
        int sA = g_srcs[i], sB = g_srcs[i + 1], sC = g_srcs[i + 2], sD = g_srcs[i + 3];
        float2 eA = g_exs[i], eB = g_exs[i + 1], eC = g_exs[i + 2], eD = g_exs[i + 3];
        float4 xA = X[(size_t)sA * 32 + lane];
        float4 xB = X[(size_t)sB * 32 + lane];
        float4 xC = X[(size_t)sC * 32 + lane];
        float4 xD = X[(size_t)sD * 32 + lane];
        float aA = h ? eA.y : eA.x;
        float aB = h ? eB.y : eB.x;
        float aC = h ? eC.y : eC.x;
        float aD = h ? eD.y : eD.x;
        acc.x += aA * xA.x + aB * xB.x + aC * xC.x + aD * xD.x;
        acc.y += aA * xA.y + aB * xB.y + aC * xC.y + aD * xD.y;
        acc.z += aA * xA.z + aB * xB.z + aC * xC.z + aD * xD.z;
        acc.w += aA * xA.w + aB * xB.w + aC * xC.w + aD * xD.w;
    }
    for (; i < end; i++) {
        int sA = g_srcs[i];
        float2 eA = g_exs[i];
        float aA = h ? eA.y : eA.x;
        float4 xA = X[(size_t)sA * 32 + lane];
        acc.x += aA * xA.x; acc.y += aA * xA.y;
        acc.z += aA * xA.z; acc.w += aA * xA.w;
    }
    ((float4*)g_agg)[(size_t)dst * 32 + lane] = acc;
}

// dense1: t1 = relu( relu(agg+bconv) @ Wlt + blt )  [N,128]->[N,64]
// 256 thr = 16 nodes x 16 colgroups (4 cols)
__global__ void k_dense1(const float* __restrict__ Wlt, const float* __restrict__ blt,
                         const float* __restrict__ bconv) {
    __shared__ float sW[128 * 64];
    __shared__ float sF[16 * 132];
    __shared__ float sb[64];
    __shared__ float sbc[128];
    int t = threadIdx.x;
    for (int i = t; i < 8192; i += 256) sW[i] = Wlt[i];
    if (t < 64)  sb[t] = blt[t];
    if (t < 128) sbc[t] = bconv[t];
    int cg = t & 15, nl = t >> 4;
    for (int base = blockIdx.x * 16; base < NN; base += gridDim.x * 16) {
        __syncthreads();
        for (int i = t; i < 2048; i += 256) {
            int n = i >> 7, k = i & 127, nd = base + n;
            float v = (nd < NN) ? g_agg[(size_t)nd * 128 + k] + sbc[k] : 0.f;
            sF[n * 132 + k] = v > 0.f ? v : 0.f;
        }
        __syncthreads();
        float4 acc = ((const float4*)sb)[cg];
        #pragma unroll 4
        for (int k = 0; k < 128; k += 4) {
            float4 f4 = *(const float4*)&sF[nl * 132 + k];
            float4 w0 = ((const float4*)sW)[(k    ) * 16 + cg];
            float4 w1 = ((const float4*)sW)[(k + 1) * 16 + cg];
            float4 w2 = ((const float4*)sW)[(k + 2) * 16 + cg];
            float4 w3 = ((const float4*)sW)[(k + 3) * 16 + cg];
            acc.x += f4.x * w0.x + f4.y * w1.x + f4.z * w2.x + f4.w * w3.x;
            acc.y += f4.x * w0.y + f4.y * w1.y + f4.z * w2.y + f4.w * w3.y;
            acc.z += f4.x * w0.z + f4.y * w1.z + f4.z * w2.z + f4.w * w3.z;
            acc.w += f4.x * w0.w + f4.y * w1.w + f4.z * w2.w + f4.w * w3.w;
        }
        int node = base + nl;
        if (node < NN) {
            acc.x = acc.x > 0.f ? acc.x : 0.f;
            acc.y = acc.y > 0.f ? acc.y : 0.f;
            acc.z = acc.z > 0.f ? acc.z : 0.f;
            acc.w = acc.w > 0.f ? acc.w : 0.f;
            ((float4*)g_t1)[(size_t)node * 16 + cg] = acc;
        }
    }
}

// dense2: t2 = t1 @ Wfm + bfm   [N,64]->[N,64]
__global__ void k_dense2(const float* __restrict__ Wfm, const float* __restrict__ bfm) {
    __shared__ float sW[64 * 64];
    __shared__ float sF[16 * 68];
    __shared__ float sb[64];
    int t = threadIdx.x;
    for (int i = t; i < 4096; i += 256) sW[i] = Wfm[i];
    if (t < 64) sb[t] = bfm[t];
    int cg = t & 15, nl = t >> 4;
    for (int base = blockIdx.x * 16; base < NN; base += gridDim.x * 16) {
        __syncthreads();
        for (int i = t; i < 1024; i += 256) {
            int n = i >> 6, k = i & 63, nd = base + n;
            sF[n * 68 + k] = (nd < NN) ? g_t1[(size_t)nd * 64 + k] : 0.f;
        }
        __syncthreads();
        float4 acc = ((const float4*)sb)[cg];
        #pragma unroll 4
        for (int k = 0; k < 64; k += 4) {
            float4 f4 = *(const float4*)&sF[nl * 68 + k];
            float4 w0 = ((const float4*)sW)[(k    ) * 16 + cg];
            float4 w1 = ((const float4*)sW)[(k + 1) * 16 + cg];
            float4 w2 = ((const float4*)sW)[(k + 2) * 16 + cg];
            float4 w3 = ((const float4*)sW)[(k + 3) * 16 + cg];
            acc.x += f4.x * w0.x + f4.y * w1.x + f4.z * w2.x + f4.w * w3.x;
            acc.y += f4.x * w0.y + f4.y * w1.y + f4.z * w2.y + f4.w * w3.y;
            acc.z += f4.x * w0.z + f4.y * w1.z + f4.z * w2.z + f4.w * w3.z;
            acc.w += f4.x * w0.w + f4.y * w1.w + f4.z * w2.w + f4.w * w3.w;
        }
        int node = base + nl;
        if (node < NN) ((float4*)g_t2)[(size_t)node * 16 + cg] = acc;
    }
}

// dense3: out = concat(lf, t2) @ Wpc + bpc   [N,128]->[N,64]
__global__ void k_dense3(const float* __restrict__ lf,
                         const float* __restrict__ Wpc, const float* __restrict__ bpc,
                         float* __restrict__ out) {
    __shared__ float sW[128 * 64];
    __shared__ float sF[16 * 132];
    __shared__ float sb[64];
    int t = threadIdx.x;
    for (int i = t; i < 8192; i += 256) sW[i] = Wpc[i];
    if (t < 64) sb[t] = bpc[t];
    int cg = t & 15, nl = t >> 4;
    for (int base = blockIdx.x * 16; base < NN; base += gridDim.x * 16) {
        __syncthreads();
        for (int i = t; i < 2048; i += 256) {
            int n = i >> 7, k = i & 127, nd = base + n;
            float v = 0.f;
            if (nd < NN)
                v = (k < 64) ? lf[(size_t)nd * 64 + k] : g_t2[(size_t)nd * 64 + (k - 64)];
            sF[n * 132 + k] = v;
        }
        __syncthreads();
        float4 acc = ((const float4*)sb)[cg];
        #pragma unroll 4
        for (int k = 0; k < 128; k += 4) {
            float4 f4 = *(const float4*)&sF[nl * 132 + k];
            float4 w0 = ((const float4*)sW)[(k    ) * 16 + cg];
            float4 w1 = ((const float4*)sW)[(k + 1) * 16 + cg];
            float4 w2 = ((const float4*)sW)[(k + 2) * 16 + cg];
            float4 w3 = ((const float4*)sW)[(k + 3) * 16 + cg];
            acc.x += f4.x * w0.x + f4.y * w1.x + f4.z * w2.x + f4.w * w3.x;
            acc.y += f4.x * w0.y + f4.y * w1.y + f4.z * w2.y + f4.w * w3.y;
            acc.z += f4.x * w0.z + f4.y * w1.z + f4.z * w2.z + f4.w * w3.z;
            acc.w += f4.x * w0.w + f4.y * w1.w + f4.z * w2.w + f4.w * w3.w;
        }
        int node = base + nl;
        if (node < NN) ((float4*)out)[(size_t)node * 16 + cg] = acc;
    }
}

// ---------------- launch ----------------
extern "C" void kernel_launch(void* const* d_in, const int* in_sizes, int n_in,
                              void* d_out, int out_size) {
    int k = (n_in >= 17) ? 5 : 4;
    const float* lf    = (const float*)d_in[0];
    const int*   ei    = (const int*)  d_in[1];
    const float* ef    = (const float*)d_in[2];
    const float* rf    = (const float*)d_in[3];
    const float* Wlin  = (const float*)d_in[k + 0];
    const float* atts  = (const float*)d_in[k + 1];
    const float* attd  = (const float*)d_in[k + 2];
    const float* Wedge = (const float*)d_in[k + 3];
    const float* atte  = (const float*)d_in[k + 4];
    const float* bconv = (const float*)d_in[k + 5];
    const float* Wlt   = (const float*)d_in[k + 6];
    const float* blt   = (const float*)d_in[k + 7];
    const float* Wfm   = (const float*)d_in[k + 8];
    const float* bfm   = (const float*)d_in[k + 9];
    const float* Wpc   = (const float*)d_in[k + 10];
    const float* bpc   = (const float*)d_in[k + 11];
    float* out = (float*)d_out;

    int hasEi  = out_size >= NN * 64 + 2 * EE;
    int hasAtt = out_size >= NN * 64 + 2 * EE + 2 * EE;

    k_zero<<<(NN + 255) / 256, 256>>>();
    k_vec<<<1, 256>>>(Wlin, attd, Wedge, atte);
    k_node<<<592, 256>>>(rf, Wlin, atts);
    k_adst<<<592, 256>>>(lf);
    k_edge_alpha<<<EE / 64, 256>>>(ef, ei);
    k_scan<<<1, 1024>>>();
    k_fill<<<(EE + 255) / 256, 256>>>(ei, out, hasEi, hasAtt);
    k_gat<<<(NN + 7) / 8, 256>>>();
    k_dense1<<<296, 256>>>(Wlt, blt, bconv);
    k_dense2<<<296, 256>>>(Wfm, bfm);
    k_dense3<<<296, 256>>>(lf, Wpc, bpc, out);
}

// round 6
// speedup vs baseline: 3.4055x; 1.6781x over previous
#include <cuda_runtime.h>

#define NN 50000
#define EE 800000
#define DD 64
#define HH 2
#define HC 128

// ---------------- scratch ----------------
__device__ float  g_x_src[(size_t)NN * HC];
__device__ float  g_a_src[NN * HH];
__device__ float  g_a_dst[NN * HH];
__device__ float2 g_ex2 [EE];                 // exp(leaky(alpha)) by edge id
__device__ float2 g_exs [EE];                 // normalized att, CSR order
__device__ int    g_srcs[EE];                 // src ids, CSR order
__device__ float2 g_sum2[NN];                 // per-dst sum of exp
__device__ float  g_agg [(size_t)NN * HC];
__device__ float  g_t1  [(size_t)NN * 64];
__device__ float  g_t2  [(size_t)NN * 64];
__device__ float  g_vedge[HH * DD];
__device__ float  g_udst [HH * DD];
__device__ int    g_deg [NN];
__device__ int    g_rs  [NN];
__device__ int    g_cur [NN];
__device__ int    g_total;

// ---------------- kernels ----------------

__global__ void k_zero() {
    int i = blockIdx.x * blockDim.x + threadIdx.x;
    if (i < NN) { g_deg[i] = 0; g_sum2[i] = make_float2(0.f, 0.f); }
    if (i == 0) g_total = 0;
}

__global__ void k_vec(const float* __restrict__ Wlin, const float* __restrict__ attd,
                      const float* __restrict__ Wedge, const float* __restrict__ atte) {
    int t = threadIdx.x;
    if (t < 128) {
        int h = t >> 6, d = t & 63;
        float acc = 0.f;
        #pragma unroll 8
        for (int c = 0; c < 64; c++) acc += Wlin[d * 128 + h * 64 + c] * attd[h * 64 + c];
        g_udst[h * 64 + d] = acc;
    } else {
        int idx = t - 128;
        int h = idx >> 6, d = idx & 63;
        float acc = 0.f;
        #pragma unroll 8
        for (int c = 0; c < 64; c++) acc += Wedge[d * 128 + h * 64 + c] * atte[h * 64 + c];
        g_vedge[h * 64 + d] = acc;
    }
}

// x_src = rf @ Wlin ; a_src = x_src.att_src ; a_dst = lf.udst
// 256 thr: cg=t&31 (4 cols), nl=t>>5 (warp); warp handles 4 nodes; block 32 nodes
__global__ void k_node(const float* __restrict__ rf, const float* __restrict__ lf,
                       const float* __restrict__ Wlin, const float* __restrict__ atts) {
    __shared__ float sF[32 * 65];
    __shared__ float sA[128], sU[128];
    int t = threadIdx.x;
    if (t < 128) { sA[t] = atts[t]; sU[t] = g_udst[t]; }
    int cg = t & 31, nl = t >> 5;
    int base = blockIdx.x * 32;
    for (int i = t; i < 2048; i += 256) {
        int n = i >> 6, k = i & 63, nd = base + n;
        sF[n * 65 + k] = (nd < NN) ? rf[(size_t)nd * 64 + k] : 0.f;
    }
    __syncthreads();
    const float4* W4 = (const float4*)Wlin;
    float4 a0 = make_float4(0,0,0,0), a1 = a0, a2 = a0, a3 = a0;
    int r0 = (nl * 4 + 0) * 65, r1 = (nl * 4 + 1) * 65,
        r2 = (nl * 4 + 2) * 65, r3 = (nl * 4 + 3) * 65;
    #pragma unroll 8
    for (int k = 0; k < 64; k++) {
        float4 w = W4[k * 32 + cg];
        float f0 = sF[r0 + k], f1 = sF[r1 + k], f2 = sF[r2 + k], f3 = sF[r3 + k];
        a0.x += f0 * w.x; a0.y += f0 * w.y; a0.z += f0 * w.z; a0.w += f0 * w.w;
        a1.x += f1 * w.x; a1.y += f1 * w.y; a1.z += f1 * w.z; a1.w += f1 * w.w;
        a2.x += f2 * w.x; a2.y += f2 * w.y; a2.z += f2 * w.z; a2.w += f2 * w.w;
        a3.x += f3 * w.x; a3.y += f3 * w.y; a3.z += f3 * w.z; a3.w += f3 * w.w;
    }
    int h = cg >> 4, c = cg & 15;
    float4 at4 = ((const float4*)sA)[cg];
    float4 u4  = ((const float4*)sU)[h * 16 + c];
    #pragma unroll
    for (int j = 0; j < 4; j++) {
        int nd = base + nl * 4 + j;
        if (nd >= NN) break;                       // warp-uniform
        float4 acc = (j == 0) ? a0 : (j == 1) ? a1 : (j == 2) ? a2 : a3;
        ((float4*)g_x_src)[(size_t)nd * 32 + cg] = acc;
        float p = acc.x * at4.x + acc.y * at4.y + acc.z * at4.z + acc.w * at4.w;
        float4 l4 = ((const float4*)lf)[(size_t)nd * 16 + c];
        float q = l4.x * u4.x + l4.y * u4.y + l4.z * u4.z + l4.w * u4.w;
        p += __shfl_xor_sync(0xffffffffu, p, 8);
        p += __shfl_xor_sync(0xffffffffu, p, 4);
        p += __shfl_xor_sync(0xffffffffu, p, 2);
        p += __shfl_xor_sync(0xffffffffu, p, 1);
        q += __shfl_xor_sync(0xffffffffu, q, 8);
        q += __shfl_xor_sync(0xffffffffu, q, 4);
        q += __shfl_xor_sync(0xffffffffu, q, 2);
        q += __shfl_xor_sync(0xffffffffu, q, 1);
        if (cg == 0)  { g_a_src[nd * 2 + 0] = p; g_a_dst[nd * 2 + 0] = q; }
        if (cg == 16) { g_a_src[nd * 2 + 1] = p; g_a_dst[nd * 2 + 1] = q; }
    }
}

// 4 lanes per edge: alpha -> leaky -> exp ; accumulate deg + sums
__global__ void k_edge_alpha(const float* __restrict__ ef, const int* __restrict__ ei) {
    __shared__ float sv[128];
    int t = threadIdx.x;
    if (t < 128) sv[t] = g_vedge[t];
    __syncthreads();
    int e = blockIdx.x * 64 + (t >> 2);
    int g = t & 3;
    const float4* E4 = (const float4*)ef;
    float4 v0 = E4[(size_t)e * 16 + g];
    float4 v1 = E4[(size_t)e * 16 + g + 4];
    float4 v2 = E4[(size_t)e * 16 + g + 8];
    float4 v3 = E4[(size_t)e * 16 + g + 12];
    const float4* S4 = (const float4*)sv;
    float4 s0, s1;
    float p0 = 0.f, p1 = 0.f;
    s0 = S4[g];      s1 = S4[16 + g];
    p0 += v0.x*s0.x + v0.y*s0.y + v0.z*s0.z + v0.w*s0.w;
    p1 += v0.x*s1.x + v0.y*s1.y + v0.z*s1.z + v0.w*s1.w;
    s0 = S4[g + 4];  s1 = S4[20 + g];
    p0 += v1.x*s0.x + v1.y*s0.y + v1.z*s0.z + v1.w*s0.w;
    p1 += v1.x*s1.x + v1.y*s1.y + v1.z*s1.z + v1.w*s1.w;
    s0 = S4[g + 8];  s1 = S4[24 + g];
    p0 += v2.x*s0.x + v2.y*s0.y + v2.z*s0.z + v2.w*s0.w;
    p1 += v2.x*s1.x + v2.y*s1.y + v2.z*s1.z + v2.w*s1.w;
    s0 = S4[g + 12]; s1 = S4[28 + g];
    p0 += v3.x*s0.x + v3.y*s0.y + v3.z*s0.z + v3.w*s0.w;
    p1 += v3.x*s1.x + v3.y*s1.y + v3.z*s1.z + v3.w*s1.w;
    float a = __shfl_xor_sync(0xffffffffu, p0, 2);
    float b = __shfl_xor_sync(0xffffffffu, p1, 2);
    float r = (g & 2) ? (p1 + b) : (p0 + a);
    r += __shfl_xor_sync(0xffffffffu, r, 1);
    float other = __shfl_xor_sync(0xffffffffu, r, 2);
    if (g == 0) {
        int src = ei[e], dst = ei[EE + e];
        float2 as = ((const float2*)g_a_src)[src];
        float2 ad = ((const float2*)g_a_dst)[dst];
        float a0 = as.x + ad.x + r;
        float a1 = as.y + ad.y + other;
        a0 = a0 > 0.f ? a0 : 0.2f * a0;
        a1 = a1 > 0.f ? a1 : 0.2f * a1;
        float e0 = __expf(a0), e1 = __expf(a1);
        g_ex2[e] = make_float2(e0, e1);
        atomicAdd(&g_deg[dst], 1);
        atomicAdd(&g_sum2[dst].x, e0);
        atomicAdd(&g_sum2[dst].y, e1);
    }
}

// CSR range allocation: block scan + one global atomic (ranges need not be ordered)
__global__ void k_alloc() {
    __shared__ int wsum[8];
    __shared__ int sbase;
    int t = threadIdx.x;
    int i = blockIdx.x * 256 + t;
    int d = (i < NN) ? g_deg[i] : 0;
    int lane = t & 31, w = t >> 5;
    int x = d;
    #pragma unroll
    for (int o = 1; o < 32; o <<= 1) {
        int v = __shfl_up_sync(0xffffffffu, x, o);
        if (lane >= o) x += v;
    }
    if (lane == 31) wsum[w] = x;
    __syncthreads();
    if (t == 0) {
        int run = 0;
        #pragma unroll
        for (int j = 0; j < 8; j++) { int v = wsum[j]; wsum[j] = run; run += v; }
        sbase = atomicAdd(&g_total, run);
    }
    __syncthreads();
    int excl = sbase + wsum[w] + x - d;
    if (i < NN) { g_rs[i] = excl; g_cur[i] = excl; }
}

// CSR fill with normalized attention; emit edge_index + att outputs coalesced
__global__ void k_fill(const int* __restrict__ ei, float* __restrict__ out,
                       int hasEi, int hasAtt) {
    int e = blockIdx.x * blockDim.x + threadIdx.x;
    if (e >= EE) return;
    int src = ei[e], dst = ei[EE + e];
    float2 ex = g_ex2[e];
    float2 sm = g_sum2[dst];
    float2 att = make_float2(ex.x / (sm.x + 1e-16f), ex.y / (sm.y + 1e-16f));
    int pos = atomicAdd(&g_cur[dst], 1);
    g_srcs[pos] = src;
    g_exs[pos]  = att;
    if (hasAtt)
        ((float2*)(out + (size_t)NN * 64 + 2 * EE))[e] = att;
    if (hasEi) {
        out[NN * 64 + e]      = (float)src;
        out[NN * 64 + EE + e] = (float)dst;
    }
}

// warp per dst: gather-accumulate (att pre-normalized)
__global__ void k_gat() {
    int dst  = (blockIdx.x * blockDim.x + threadIdx.x) >> 5;
    int lane = threadIdx.x & 31;
    if (dst >= NN) return;
    int beg = g_rs[dst], end = beg + g_deg[dst];
    int h = lane >> 4;
    float4 acc = make_float4(0.f, 0.f, 0.f, 0.f);
    const float4* X = (const float4*)g_x_src;
    int i = beg;
    for (; i + 4 <= end; i += 4) {
        int sA = g_srcs[i], sB = g_srcs[i + 1], sC = g_srcs[i + 2], sD = g_srcs[i + 3];
        float2 eA = g_exs[i], eB = g_exs[i + 1], eC = g_exs[i + 2], eD = g_exs[i + 3];
        float4 xA = X[(size_t)sA * 32 + lane];
        float4 xB = X[(size_t)sB * 32 + lane];
        float4 xC = X[(size_t)sC * 32 + lane];
        float4 xD = X[(size_t)sD * 32 + lane];
        float aA = h ? eA.y : eA.x;
        float aB = h ? eB.y : eB.x;
        float aC = h ? eC.y : eC.x;
        float aD = h ? eD.y : eD.x;
        acc.x += aA * xA.x + aB * xB.x + aC * xC.x + aD * xD.x;
        acc.y += aA * xA.y + aB * xB.y + aC * xC.y + aD * xD.y;
        acc.z += aA * xA.z + aB * xB.z + aC * xC.z + aD * xD.z;
        acc.w += aA * xA.w + aB * xB.w + aC * xC.w + aD * xD.w;
    }
    for (; i < end; i++) {
        int sA = g_srcs[i];
        float2 eA = g_exs[i];
        float aA = h ? eA.y : eA.x;
        float4 xA = X[(size_t)sA * 32 + lane];
        acc.x += aA * xA.x; acc.y += aA * xA.y;
        acc.z += aA * xA.z; acc.w += aA * xA.w;
    }
    ((float4*)g_agg)[(size_t)dst * 32 + lane] = acc;
}

// dense1: t1 = relu( relu(agg+bconv) @ Wlt + blt )  [N,128]->[N,64]
// 128 thr: cg=t&15, nl=t>>4 (8 lanes x 4 nodes = 32 nodes); W from gmem (L1)
__global__ void k_dense1(const float* __restrict__ Wlt, const float* __restrict__ blt,
                         const float* __restrict__ bconv) {
    __shared__ float sF[32 * 128];
    __shared__ float sbc[128];
    int t = threadIdx.x;
    if (t < 128) sbc[t] = bconv[t];
    int base = blockIdx.x * 32;
    __syncthreads();
    for (int i = t; i < 4096; i += 128) {
        int n = i >> 7, k = i & 127, nd = base + n;
        float v = (nd < NN) ? g_agg[(size_t)nd * 128 + k] + sbc[k] : 0.f;
        sF[i] = v > 0.f ? v : 0.f;
    }
    __syncthreads();
    int cg = t & 15, nl = t >> 4;
    const float4* W4 = (const float4*)Wlt;
    float4 a0 = make_float4(0,0,0,0), a1 = a0, a2 = a0, a3 = a0;
    int r0 = (nl * 4 + 0) * 128, r1 = (nl * 4 + 1) * 128,
        r2 = (nl * 4 + 2) * 128, r3 = (nl * 4 + 3) * 128;
    #pragma unroll 8
    for (int k = 0; k < 128; k++) {
        float4 w = W4[k * 16 + cg];
        float f0 = sF[r0 + k], f1 = sF[r1 + k], f2 = sF[r2 + k], f3 = sF[r3 + k];
        a0.x += f0 * w.x; a0.y += f0 * w.y; a0.z += f0 * w.z; a0.w += f0 * w.w;
        a1.x += f1 * w.x; a1.y += f1 * w.y; a1.z += f1 * w.z; a1.w += f1 * w.w;
        a2.x += f2 * w.x; a2.y += f2 * w.y; a2.z += f2 * w.z; a2.w += f2 * w.w;
        a3.x += f3 * w.x; a3.y += f3 * w.y; a3.z += f3 * w.z; a3.w += f3 * w.w;
    }
    float4 b4 = ((const float4*)blt)[cg];
    #pragma unroll
    for (int j = 0; j < 4; j++) {
        int nd = base + nl * 4 + j;
        if (nd >= NN) break;
        float4 acc = (j == 0) ? a0 : (j == 1) ? a1 : (j == 2) ? a2 : a3;
        acc.x += b4.x; acc.y += b4.y; acc.z += b4.z; acc.w += b4.w;
        acc.x = acc.x > 0.f ? acc.x : 0.f;
        acc.y = acc.y > 0.f ? acc.y : 0.f;
        acc.z = acc.z > 0.f ? acc.z : 0.f;
        acc.w = acc.w > 0.f ? acc.w : 0.f;
        ((float4*)g_t1)[(size_t)nd * 16 + cg] = acc;
    }
}

// dense2: t2 = t1 @ Wfm + bfm   [N,64]->[N,64]
__global__ void k_dense2(const float* __restrict__ Wfm, const float* __restrict__ bfm) {
    __shared__ float sF[32 * 64];
    int t = threadIdx.x;
    int base = blockIdx.x * 32;
    for (int i = t; i < 2048; i += 128) {
        int n = i >> 6, k = i & 63, nd = base + n;
        sF[i] = (nd < NN) ? g_t1[(size_t)nd * 64 + k] : 0.f;
    }
    __syncthreads();
    int cg = t & 15, nl = t >> 4;
    const float4* W4 = (const float4*)Wfm;
    float4 a0 = make_float4(0,0,0,0), a1 = a0, a2 = a0, a3 = a0;
    int r0 = (nl * 4 + 0) * 64, r1 = (nl * 4 + 1) * 64,
        r2 = (nl * 4 + 2) * 64, r3 = (nl * 4 + 3) * 64;
    #pragma unroll 8
    for (int k = 0; k < 64; k++) {
        float4 w = W4[k * 16 + cg];
        float f0 = sF[r0 + k], f1 = sF[r1 + k], f2 = sF[r2 + k], f3 = sF[r3 + k];
        a0.x += f0 * w.x; a0.y += f0 * w.y; a0.z += f0 * w.z; a0.w += f0 * w.w;
        a1.x += f1 * w.x; a1.y += f1 * w.y; a1.z += f1 * w.z; a1.w += f1 * w.w;
        a2.x += f2 * w.x; a2.y += f2 * w.y; a2.z += f2 * w.z; a2.w += f2 * w.w;
        a3.x += f3 * w.x; a3.y += f3 * w.y; a3.z += f3 * w.z; a3.w += f3 * w.w;
    }
    float4 b4 = ((const float4*)bfm)[cg];
    #pragma unroll
    for (int j = 0; j < 4; j++) {
        int nd = base + nl * 4 + j;
        if (nd >= NN) break;
        float4 acc = (j == 0) ? a0 : (j == 1) ? a1 : (j == 2) ? a2 : a3;
        acc.x += b4.x; acc.y += b4.y; acc.z += b4.z; acc.w += b4.w;
        ((float4*)g_t2)[(size_t)nd * 16 + cg] = acc;
    }
}

// dense3: out = concat(lf, t2) @ Wpc + bpc   [N,128]->[N,64]
__global__ void k_dense3(const float* __restrict__ lf,
                         const float* __restrict__ Wpc, const float* __restrict__ bpc,
                         float* __restrict__ out) {
    __shared__ float sF[32 * 128];
    int t = threadIdx.x;
    int base = blockIdx.x * 32;
    for (int i = t; i < 4096; i += 128) {
        int n = i >> 7, k = i & 127, nd = base + n;
        float v = 0.f;
        if (nd < NN)
            v = (k < 64) ? lf[(size_t)nd * 64 + k] : g_t2[(size_t)nd * 64 + (k - 64)];
        sF[i] = v;
    }
    __syncthreads();
    int cg = t & 15, nl = t >> 4;
    const float4* W4 = (const float4*)Wpc;
    float4 a0 = make_float4(0,0,0,0), a1 = a0, a2 = a0, a3 = a0;
    int r0 = (nl * 4 + 0) * 128, r1 = (nl * 4 + 1) * 128,
        r2 = (nl * 4 + 2) * 128, r3 = (nl * 4 + 3) * 128;
    #pragma unroll 8
    for (int k = 0; k < 128; k++) {
        float4 w = W4[k * 16 + cg];
        float f0 = sF[r0 + k], f1 = sF[r1 + k], f2 = sF[r2 + k], f3 = sF[r3 + k];
        a0.x += f0 * w.x; a0.y += f0 * w.y; a0.z += f0 * w.z; a0.w += f0 * w.w;
        a1.x += f1 * w.x; a1.y += f1 * w.y; a1.z += f1 * w.z; a1.w += f1 * w.w;
        a2.x += f2 * w.x; a2.y += f2 * w.y; a2.z += f2 * w.z; a2.w += f2 * w.w;
        a3.x += f3 * w.x; a3.y += f3 * w.y; a3.z += f3 * w.z; a3.w += f3 * w.w;
    }
    float4 b4 = ((const float4*)bpc)[cg];
    #pragma unroll
    for (int j = 0; j < 4; j++) {
        int nd = base + nl * 4 + j;
        if (nd >= NN) break;
        float4 acc = (j == 0) ? a0 : (j == 1) ? a1 : (j == 2) ? a2 : a3;
        acc.x += b4.x; acc.y += b4.y; acc.z += b4.z; acc.w += b4.w;
        ((float4*)out)[(size_t)nd * 16 + cg] = acc;
    }
}

// ---------------- launch ----------------
extern "C" void kernel_launch(void* const* d_in, const int* in_sizes, int n_in,
                              void* d_out, int out_size) {
    int k = (n_in >= 17) ? 5 : 4;
    const float* lf    = (const float*)d_in[0];
    const int*   ei    = (const int*)  d_in[1];
    const float* ef    = (const float*)d_in[2];
    const float* rf    = (const float*)d_in[3];
    const float* Wlin  = (const float*)d_in[k + 0];
    const float* atts  = (const float*)d_in[k + 1];
    const float* attd  = (const float*)d_in[k + 2];
    const float* Wedge = (const float*)d_in[k + 3];
    const float* atte  = (const float*)d_in[k + 4];
    const float* bconv = (const float*)d_in[k + 5];
    const float* Wlt   = (const float*)d_in[k + 6];
    const float* blt   = (const float*)d_in[k + 7];
    const float* Wfm   = (const float*)d_in[k + 8];
    const float* bfm   = (const float*)d_in[k + 9];
    const float* Wpc   = (const float*)d_in[k + 10];
    const float* bpc   = (const float*)d_in[k + 11];
    float* out = (float*)d_out;

    int hasEi  = out_size >= NN * 64 + 2 * EE;
    int hasAtt = out_size >= NN * 64 + 2 * EE + 2 * EE;

    int nblk = (NN + 31) / 32;  // 1563
    k_zero<<<(NN + 255) / 256, 256>>>();
    k_vec<<<1, 256>>>(Wlin, attd, Wedge, atte);
    k_node<<<nblk, 256>>>(rf, lf, Wlin, atts);
    k_edge_alpha<<<EE / 64, 256>>>(ef, ei);      // profiled slot
    k_alloc<<<(NN + 255) / 256, 256>>>();
    k_fill<<<(EE + 255) / 256, 256>>>(ei, out, hasEi, hasAtt);
    k_gat<<<(NN + 7) / 8, 256>>>();
    k_dense1<<<nblk, 128>>>(Wlt, blt, bconv);
    k_dense2<<<nblk, 128>>>(Wfm, bfm);
    k_dense3<<<nblk, 128>>>(lf, Wpc, bpc, out);
}